// round 3
// baseline (speedup 1.0000x reference)
#include <cuda_runtime.h>
#include <cuda_bf16.h>

#define M 4096
#define LYRS 32
#define K 64
#define NBLK 128
#define NTHR 512
#define NODES_PER_BLK (M / NBLK)             // 32
#define THR_PER_NODE  (NTHR / NODES_PER_BLK) // 16
#define K_PER_THR     (K / THR_PER_NODE)     // 4
#define NWARP (NTHR / 32)                    // 16
#define FLAGS_PER_WARP (NBLK / NWARP)        // 8
#define FLOATS_PER_WARP (M / NWARP)          // 256

// Double-buffered node values + per-block completion flags.
// Flags are monotonically increasing across graph replays; each block reads
// its OWN flag at entry as the epoch base (only the owner writes it, and all
// blocks perform the same number of arrives per launch, so bases agree).
__device__ float g_v[2][M];
__device__ unsigned g_flags[NBLK];

__device__ __forceinline__ unsigned ld_acq(const unsigned* p) {
    unsigned v;
    asm volatile("ld.acquire.gpu.u32 %0, [%1];" : "=r"(v) : "l"(p) : "memory");
    return v;
}
__device__ __forceinline__ void st_rel(unsigned* p, unsigned v) {
    asm volatile("st.release.gpu.u32 [%0], %1;" :: "l"(p), "r"(v) : "memory");
}

__global__ void __launch_bounds__(NTHR, 1)
net_kernel(const float* __restrict__ x,
           const float* __restrict__ w_in,
           const float* __restrict__ b_in,
           const float* __restrict__ w,
           const float* __restrict__ b,
           const int*   __restrict__ igraf,
           float* __restrict__ out)
{
    __shared__ float s_v[M];   // 16 KB staged value vector

    const int tid  = threadIdx.x;
    const int bid  = blockIdx.x;
    const int wid  = tid >> 5;
    const int lane = tid & 31;

    // Epoch base: own flag, written only by this block.
    const unsigned base = *(volatile unsigned*)&g_flags[bid];

    const int node_local   = tid >> 4;         // 0..31
    const int lane_in_node = tid & 15;         // 0..15
    const int node         = bid * NODES_PER_BLK + node_local;

    const size_t koff = (size_t)node * K + (size_t)lane_in_node * K_PER_THR;
    const float4* wp = reinterpret_cast<const float4*>(w + koff);
    const int4*   gp = reinterpret_cast<const int4*>(igraf + koff);
    const size_t  lstride4 = (size_t)M * K / 4;

    // Prefetch layer 0 operands — latency overlaps the input layer + barrier.
    float4 wr = __ldg(wp);
    int4   gr = __ldg(gp);
    float  br = __ldg(b + node);

    // ---- input layer: this block's 32 nodes, coalesced 128B store ----
    if (tid < NODES_PER_BLK) {
        int i = bid * NODES_PER_BLK + tid;
        float v0 = fmaf(w_in[i], x[i], b_in[i]);
        __stcg(&g_v[0][i], fmaxf(v0, 0.0f));
    }
    __syncthreads();
    if (tid == 0) st_rel(&g_flags[bid], base + 1);   // arrive #1

    #pragma unroll 1
    for (int l = 0; l < LYRS; ++l) {
        const int cur = l & 1;
        const unsigned target = base + 1 + (unsigned)l;

        // Fused barrier-wait + v-staging:
        // warp `wid` waits on the 8 producer blocks of its 256-float region,
        // then copies that region (1 KB) from L2 into smem.
        if (lane < FLAGS_PER_WARP) {
            const unsigned* f = &g_flags[wid * FLAGS_PER_WARP + lane];
            while ((int)(ld_acq(f) - target) < 0) { }
        }
        __syncwarp();
        {
            const float4* src = reinterpret_cast<const float4*>(&g_v[cur][wid * FLOATS_PER_WARP]);
            float4* dst = reinterpret_cast<float4*>(&s_v[wid * FLOATS_PER_WARP]);
            dst[lane]      = __ldcg(src + lane);
            dst[lane + 32] = __ldcg(src + lane + 32);
        }
        __syncthreads();

        // 4 gathered MACs per thread from shared memory.
        float acc;
        acc = wr.x * s_v[gr.x];
        acc = fmaf(wr.y, s_v[gr.y], acc);
        acc = fmaf(wr.z, s_v[gr.z], acc);
        acc = fmaf(wr.w, s_v[gr.w], acc);
        float bcur = br;

        // Prefetch next layer's operands — overlaps reduce + store + poll.
        if (l + 1 < LYRS) {
            wr = __ldg(wp + (size_t)(l + 1) * lstride4);
            gr = __ldg(gp + (size_t)(l + 1) * lstride4);
            br = __ldg(b + (size_t)(l + 1) * M + node);
        }

        // Reduce across the 16-lane node subgroup.
        acc += __shfl_xor_sync(0xffffffffu, acc, 1);
        acc += __shfl_xor_sync(0xffffffffu, acc, 2);
        acc += __shfl_xor_sync(0xffffffffu, acc, 4);
        acc += __shfl_xor_sync(0xffffffffu, acc, 8);

        if (lane_in_node == 0) {
            float val = 1.0f / (1.0f + __expf(-(acc + bcur)));
            if (l == LYRS - 1) {
                if (node == M - 1) out[0] = val;    // final scalar, no arrive
            } else {
                __stcg(&g_v[cur ^ 1][node], val);
            }
        }

        if (l + 1 < LYRS) {
            __syncthreads();                        // all 32 values stored
            if (tid == 0) st_rel(&g_flags[bid], base + 2 + (unsigned)l);
        }
    }
}

extern "C" void kernel_launch(void* const* d_in, const int* in_sizes, int n_in,
                              void* d_out, int out_size) {
    const float* x     = (const float*)d_in[0];
    const float* w_in  = (const float*)d_in[1];
    const float* b_in  = (const float*)d_in[2];
    const float* w     = (const float*)d_in[3];
    const float* b     = (const float*)d_in[4];
    const int*   igraf = (const int*)d_in[5];
    float* out = (float*)d_out;

    net_kernel<<<NBLK, NTHR>>>(x, w_in, b_in, w, b, igraf, out);
}

// round 4
// speedup vs baseline: 2.5960x; 2.5960x over previous
#include <cuda_runtime.h>
#include <cuda_bf16.h>

#define M 4096
#define LYRS 32
#define K 64
#define NBLK 128                              // compute blocks
#define NTHR 512
#define NODES_PER_BLK (M / NBLK)              // 32
#define THR_PER_NODE  (NTHR / NODES_PER_BLK)  // 16
#define K_PER_THR     (K / THR_PER_NODE)      // 4
#define OWNER_BID     (NBLK - 1)              // block owning node M-1

// Double-buffered node values.
__device__ float g_v[2][M];
// Per-block arrive flags, one per 128B line (no LTS serialization, no
// partition hot-spotting). Monotonic across graph replays.
__device__ unsigned g_arrive[NBLK * 32];
// Broadcast "go" counter, published only by the aggregator block.
__device__ unsigned g_go;

__device__ __forceinline__ unsigned ld_relx(const unsigned* p) {
    unsigned v;
    asm volatile("ld.relaxed.gpu.u32 %0, [%1];" : "=r"(v) : "l"(p) : "memory");
    return v;
}
__device__ __forceinline__ unsigned ld_acq(const unsigned* p) {
    unsigned v;
    asm volatile("ld.acquire.gpu.u32 %0, [%1];" : "=r"(v) : "l"(p) : "memory");
    return v;
}
__device__ __forceinline__ void st_rel(unsigned* p, unsigned v) {
    asm volatile("st.release.gpu.u32 [%0], %1;" :: "l"(p), "r"(v) : "memory");
}
__device__ __forceinline__ void fence_acq_rel() {
    asm volatile("fence.acq_rel.gpu;" ::: "memory");
}

__global__ void __launch_bounds__(NTHR, 1)
net_kernel(const float* __restrict__ x,
           const float* __restrict__ w_in,
           const float* __restrict__ b_in,
           const float* __restrict__ w,
           const float* __restrict__ b,
           const int*   __restrict__ igraf,
           float* __restrict__ out)
{
    const int tid  = threadIdx.x;
    const int bid  = blockIdx.x;

    // ---------------- aggregator block ----------------
    if (bid == NBLK) {
        if (tid >= 32) return;                 // one warp only
        const int lane = tid;
        // Epoch base: g_go is written only by this block; every compute
        // block reads it before its first arrive, and we publish base+1
        // only after all first arrives — so this read is race-free.
        const unsigned base = ld_relx(&g_go);
        for (int s = 1; s <= LYRS; ++s) {
            const unsigned t = base + (unsigned)s;
            bool mine;
            do {
                unsigned a0 = ld_relx(&g_arrive[(lane      ) * 32]);
                unsigned a1 = ld_relx(&g_arrive[(lane + 32 ) * 32]);
                unsigned a2 = ld_relx(&g_arrive[(lane + 64 ) * 32]);
                unsigned a3 = ld_relx(&g_arrive[(lane + 96 ) * 32]);
                mine = ((int)(a0 - t) >= 0) & ((int)(a1 - t) >= 0) &
                       ((int)(a2 - t) >= 0) & ((int)(a3 - t) >= 0);
            } while (!__all_sync(0xffffffffu, mine));
            fence_acq_rel();                   // relay: order observes < publish
            if (lane == 0) st_rel(&g_go, t);
        }
        return;
    }

    // ---------------- compute blocks ----------------
    __shared__ float s_v[M];                   // 16 KB staged value vector

    const unsigned base = ld_relx(&g_go);      // stable until first publish

    const int node_local   = tid >> 4;         // 0..31
    const int lane_in_node = tid & 15;         // 0..15
    const int node         = bid * NODES_PER_BLK + node_local;

    const size_t koff = (size_t)node * K + (size_t)lane_in_node * K_PER_THR;
    const float4* wp = reinterpret_cast<const float4*>(w + koff);
    const int4*   gp = reinterpret_cast<const int4*>(igraf + koff);
    const size_t  lstride4 = (size_t)M * K / 4;

    // Prefetch layer 0 operands — overlaps input layer + first wait.
    float4 wr = __ldg(wp);
    int4   gr = __ldg(gp);
    float  br = __ldg(b + node);

    // Input layer: this block's 32 nodes (coalesced 128B load/store).
    if (tid < NODES_PER_BLK) {
        int i = bid * NODES_PER_BLK + tid;
        float v0 = fmaf(w_in[i], x[i], b_in[i]);
        __stcg(&g_v[0][i], fmaxf(v0, 0.0f));
    }
    __syncthreads();
    if (tid == 0) st_rel(&g_arrive[bid * 32], base + 1);   // stage 1 ready

    const int last_l = (bid == OWNER_BID) ? LYRS : (LYRS - 1);

    #pragma unroll 1
    for (int l = 0; l < last_l; ++l) {
        const int cur = l & 1;

        // Wait for stage l+1 (single poller, then block-wide wake).
        if (tid == 0) {
            const unsigned t = base + 1 + (unsigned)l;
            while ((int)(ld_acq(&g_go) - t) < 0) { }
        }
        __syncthreads();

        // Stage v into shared memory: 2 coalesced float4 per thread.
        {
            const float4* src = reinterpret_cast<const float4*>(g_v[cur]);
            float4* dst = reinterpret_cast<float4*>(s_v);
            dst[tid]        = __ldcg(src + tid);
            dst[tid + NTHR] = __ldcg(src + tid + NTHR);
        }
        __syncthreads();

        // 4 gathered MACs from shared memory.
        float acc;
        acc = wr.x * s_v[gr.x];
        acc = fmaf(wr.y, s_v[gr.y], acc);
        acc = fmaf(wr.z, s_v[gr.z], acc);
        acc = fmaf(wr.w, s_v[gr.w], acc);
        float bcur = br;

        // Prefetch next layer — overlaps reduce + store + wait.
        if (l + 1 < last_l) {
            wr = __ldg(wp + (size_t)(l + 1) * lstride4);
            gr = __ldg(gp + (size_t)(l + 1) * lstride4);
            br = __ldg(b + (size_t)(l + 1) * M + node);
        }

        // Reduce across the 16-lane node subgroup.
        acc += __shfl_xor_sync(0xffffffffu, acc, 1);
        acc += __shfl_xor_sync(0xffffffffu, acc, 2);
        acc += __shfl_xor_sync(0xffffffffu, acc, 4);
        acc += __shfl_xor_sync(0xffffffffu, acc, 8);

        if (lane_in_node == 0) {
            float val = 1.0f / (1.0f + __expf(-(acc + bcur)));
            if (l == LYRS - 1) {
                if (node == M - 1) out[0] = val;       // final scalar
            } else {
                __stcg(&g_v[cur ^ 1][node], val);
            }
        }

        // Arrive for stage l+2 (not needed after the last internal layer).
        if (l < LYRS - 1) {
            __syncthreads();
            if (tid == 0) st_rel(&g_arrive[bid * 32], base + 2 + (unsigned)l);
        }
    }
}

extern "C" void kernel_launch(void* const* d_in, const int* in_sizes, int n_in,
                              void* d_out, int out_size) {
    const float* x     = (const float*)d_in[0];
    const float* w_in  = (const float*)d_in[1];
    const float* b_in  = (const float*)d_in[2];
    const float* w     = (const float*)d_in[3];
    const float* b     = (const float*)d_in[4];
    const int*   igraf = (const int*)d_in[5];
    float* out = (float*)d_out;

    net_kernel<<<NBLK + 1, NTHR>>>(x, w_in, b_in, w, b, igraf, out);
}

// round 5
// speedup vs baseline: 2.8446x; 1.0958x over previous
#include <cuda_runtime.h>
#include <cuda_bf16.h>

#define M 4096
#define LYRS 32
#define K 64
#define NBLK 128
#define NTHR 512
#define NODES_PER_BLK (M / NBLK)              // 32
#define THR_PER_NODE  (NTHR / NODES_PER_BLK)  // 16
#define K_PER_THR     (K / THR_PER_NODE)      // 4
#define OWNER_BID     (NBLK - 1)              // block owning node M-1

// Double-buffered node values.
__device__ float g_v[2][M];
// Per-block arrive flags, one per 128B line. Monotonic across graph replays.
__device__ unsigned g_arrive[NBLK * 32];

__device__ __forceinline__ unsigned ld_relx(const unsigned* p) {
    unsigned v;
    asm volatile("ld.relaxed.gpu.u32 %0, [%1];" : "=r"(v) : "l"(p) : "memory");
    return v;
}
__device__ __forceinline__ void st_rel(unsigned* p, unsigned v) {
    asm volatile("st.release.gpu.u32 [%0], %1;" :: "l"(p), "r"(v) : "memory");
}
__device__ __forceinline__ void fence_acq_rel() {
    asm volatile("fence.acq_rel.gpu;" ::: "memory");
}

__global__ void __launch_bounds__(NTHR, 1)
net_kernel(const float* __restrict__ x,
           const float* __restrict__ w_in,
           const float* __restrict__ b_in,
           const float* __restrict__ w,
           const float* __restrict__ b,
           const int*   __restrict__ igraf,
           float* __restrict__ out)
{
    __shared__ float s_v[M];                   // 16 KB staged value vector

    const int tid  = threadIdx.x;
    const int bid  = blockIdx.x;
    const int lane = tid & 31;

    // Epoch base: own flag (only this block writes it; all blocks advance by
    // the same count per launch, so bases agree across blocks).
    const unsigned base = ld_relx(&g_arrive[bid * 32]);

    const int node_local   = tid >> 4;         // 0..31
    const int lane_in_node = tid & 15;         // 0..15
    const int node         = bid * NODES_PER_BLK + node_local;

    const size_t koff = (size_t)node * K + (size_t)lane_in_node * K_PER_THR;
    const float4* wp = reinterpret_cast<const float4*>(w + koff);
    const int4*   gp = reinterpret_cast<const int4*>(igraf + koff);
    const size_t  lstride4 = (size_t)M * K / 4;

    // Prefetch layer 0 operands — overlaps input layer + first wait.
    float4 wr = __ldg(wp);
    int4   gr = __ldg(gp);
    float  br = __ldg(b + node);

    // Input layer: this block's 32 nodes.
    if (tid < NODES_PER_BLK) {
        int i = bid * NODES_PER_BLK + tid;
        float v0 = fmaf(w_in[i], x[i], b_in[i]);
        __stcg(&g_v[0][i], fmaxf(v0, 0.0f));
    }
    __syncthreads();
    if (tid == 0) st_rel(&g_arrive[bid * 32], base + 1);   // stage 1 ready

    const int last_l = (bid == OWNER_BID) ? LYRS : (LYRS - 1);

    #pragma unroll 1
    for (int l = 0; l < last_l; ++l) {
        const int cur = l & 1;
        const unsigned target = base + 1 + (unsigned)l;

        // Direct wait: warp 0 ballot-polls all 128 per-block flags
        // (4 per lane, each flag on its own 128B line, relaxed loads).
        if (tid < 32) {
            bool mine;
            do {
                unsigned a0 = ld_relx(&g_arrive[(lane      ) * 32]);
                unsigned a1 = ld_relx(&g_arrive[(lane + 32 ) * 32]);
                unsigned a2 = ld_relx(&g_arrive[(lane + 64 ) * 32]);
                unsigned a3 = ld_relx(&g_arrive[(lane + 96 ) * 32]);
                mine = ((int)(a0 - target) >= 0) & ((int)(a1 - target) >= 0) &
                       ((int)(a2 - target) >= 0) & ((int)(a3 - target) >= 0);
            } while (!__all_sync(0xffffffffu, mine));
            fence_acq_rel();    // acquire: observed releases -> v loads below
        }
        __syncthreads();

        // Stage v into shared memory: 2 coalesced float4 per thread.
        {
            const float4* src = reinterpret_cast<const float4*>(g_v[cur]);
            float4* dst = reinterpret_cast<float4*>(s_v);
            dst[tid]        = __ldcg(src + tid);
            dst[tid + NTHR] = __ldcg(src + tid + NTHR);
        }
        __syncthreads();

        // 4 gathered MACs from shared memory.
        float acc;
        acc = wr.x * s_v[gr.x];
        acc = fmaf(wr.y, s_v[gr.y], acc);
        acc = fmaf(wr.z, s_v[gr.z], acc);
        acc = fmaf(wr.w, s_v[gr.w], acc);
        float bcur = br;

        // Prefetch next layer — overlaps reduce + store + wait.
        if (l + 1 < last_l) {
            wr = __ldg(wp + (size_t)(l + 1) * lstride4);
            gr = __ldg(gp + (size_t)(l + 1) * lstride4);
            br = __ldg(b + (size_t)(l + 1) * M + node);
        }

        // Reduce across the 16-lane node subgroup.
        acc += __shfl_xor_sync(0xffffffffu, acc, 1);
        acc += __shfl_xor_sync(0xffffffffu, acc, 2);
        acc += __shfl_xor_sync(0xffffffffu, acc, 4);
        acc += __shfl_xor_sync(0xffffffffu, acc, 8);

        if (lane_in_node == 0) {
            float val = 1.0f / (1.0f + __expf(-(acc + bcur)));
            if (l == LYRS - 1) {
                if (node == M - 1) out[0] = val;       // final scalar
            } else {
                __stcg(&g_v[cur ^ 1][node], val);
            }
        }

        // Arrive for stage l+2 (skip after last internal layer).
        if (l < LYRS - 1) {
            __syncthreads();
            if (tid == 0) st_rel(&g_arrive[bid * 32], base + 2 + (unsigned)l);
        }
    }
}

extern "C" void kernel_launch(void* const* d_in, const int* in_sizes, int n_in,
                              void* d_out, int out_size) {
    const float* x     = (const float*)d_in[0];
    const float* w_in  = (const float*)d_in[1];
    const float* b_in  = (const float*)d_in[2];
    const float* w     = (const float*)d_in[3];
    const float* b     = (const float*)d_in[4];
    const int*   igraf = (const int*)d_in[5];
    float* out = (float*)d_out;

    net_kernel<<<NBLK, NTHR>>>(x, w_in, b_in, w, b, igraf, out);
}